// round 7
// baseline (speedup 1.0000x reference)
#include <cuda_runtime.h>
#include <cuda_bf16.h>
#include <cstdint>

#define B_ 1024
#define T_ 128

typedef unsigned short u16;
typedef uint32_t u32;

// ---------------- static device buffers (plain row-major, k-contiguous) ----------------
__device__ __align__(16) u16 W1hi[512 * 1024], W1lo[512 * 1024];   // [n][k]
__device__ __align__(16) u16 W3hi[512 * 1024], W3lo[512 * 1024];
__device__ __align__(16) u16 Wghi[2048 * 1024], Wglo[2048 * 1024]; // [p=4i+q][k over x|h]
__device__ __align__(16) u16 Hhi[2][B_ * 512], Hlo[2][B_ * 512];
__device__ __align__(16) u16 Chi[B_ * 512], Clo[B_ * 512];
__device__ __align__(16) u16 Z1hi[B_ * 512], Z1lo[B_ * 512];
__device__ __align__(16) u16 Xhi[B_ * 512],  Xlo[B_ * 512];
__device__ __align__(16) u16 Z2hi[(size_t)T_ * B_ * 512], Z2lo[(size_t)T_ * B_ * 512];
__device__ float g_c[B_ * 512];
__device__ float g_bgp[2048];

// ---------------- helpers ----------------
__device__ __forceinline__ u32 swz(u32 o) { return o ^ ((o >> 3) & 0x70); }
__device__ __forceinline__ u32 s2u(const void* p) {
    u32 a;
    asm("{ .reg .u64 t; cvta.to.shared.u64 t, %1; cvt.u32.u64 %0, t; }" : "=r"(a) : "l"(p));
    return a;
}
__device__ __forceinline__ void cp16(u32 dst, const void* src) {
    asm volatile("cp.async.cg.shared.global [%0], [%1], 16;" :: "r"(dst), "l"(src));
}
__device__ __forceinline__ void cp_commit() { asm volatile("cp.async.commit_group;" ::: "memory"); }
template <int N> __device__ __forceinline__ void cp_wait() {
    asm volatile("cp.async.wait_group %0;" :: "n"(N) : "memory");
}
__device__ __forceinline__ void ldsm4(u32* r, u32 a) {
    asm volatile("ldmatrix.sync.aligned.m8n8.x4.shared.b16 {%0,%1,%2,%3}, [%4];"
                 : "=r"(r[0]), "=r"(r[1]), "=r"(r[2]), "=r"(r[3]) : "r"(a));
}
__device__ __forceinline__ void hmma(float* c, const u32* a, u32 b0, u32 b1) {
    asm volatile("mma.sync.aligned.m16n8k16.row.col.f32.bf16.bf16.f32 "
                 "{%0,%1,%2,%3}, {%4,%5,%6,%7}, {%8,%9}, {%0,%1,%2,%3};"
                 : "+f"(c[0]), "+f"(c[1]), "+f"(c[2]), "+f"(c[3])
                 : "r"(a[0]), "r"(a[1]), "r"(a[2]), "r"(a[3]), "r"(b0), "r"(b1));
}
__device__ __forceinline__ void split1(float v, u16& h, u16& l) {
    __nv_bfloat16 hb = __float2bfloat16(v);
    __nv_bfloat16 lb = __float2bfloat16(v - __bfloat162float(hb));
    h = __bfloat16_as_ushort(hb);
    l = __bfloat16_as_ushort(lb);
}
__device__ __forceinline__ void split2(float a, float b, u32& hi, u32& lo) {
    u16 ah, al, bh, bl;
    split1(a, ah, al); split1(b, bh, bl);
    hi = (u32)ah | ((u32)bh << 16);
    lo = (u32)al | ((u32)bl << 16);
}
__device__ __forceinline__ float sigf(float x) { return 1.f / (1.f + expf(-x)); }

// ---------------- prep: split weights, biases, zero state ----------------
__global__ __launch_bounds__(256) void prep_w(
    const float* __restrict__ W1, const float* __restrict__ W3,
    const float* __restrict__ Wih, const float* __restrict__ Whh,
    const float* __restrict__ bih, const float* __restrict__ bhh)
{
    const int N1 = 524288, N2 = 1048576, N3 = N2 + 2097152;
    const int N4 = N3 + 2048, N5 = N4 + 1048576, N6 = N5 + 524288;
    for (int idx = blockIdx.x * blockDim.x + threadIdx.x; idx < N6;
         idx += gridDim.x * blockDim.x) {
        if (idx < N2) {
            int j = (idx < N1) ? idx : idx - N1;
            float v = (idx < N1) ? W1[j] : W3[j];
            u16 h, l; split1(v, h, l);
            if (idx < N1) { W1hi[j] = h; W1lo[j] = l; }
            else          { W3hi[j] = h; W3lo[j] = l; }
        } else if (idx < N3) {
            int j = idx - N2;
            int p = j >> 10, k = j & 1023;
            int r = (p & 3) * 512 + (p >> 2);
            float v = (k < 512) ? Wih[r * 512 + k] : Whh[r * 512 + (k - 512)];
            u16 h, l; split1(v, h, l);
            Wghi[j] = h; Wglo[j] = l;
        } else if (idx < N4) {
            int p = idx - N3, i = p >> 2, q = p & 3;
            g_bgp[p] = bih[q * 512 + i] + bhh[q * 512 + i];
        } else if (idx < N5) {
            int j = idx - N4;
            int sel = j >> 18, w = j & 262143;
            u16* b = (sel == 0) ? Hhi[0] : (sel == 1) ? Hlo[0] : (sel == 2) ? Chi : Clo;
            *(u32*)&b[w * 2] = 0u;
        } else g_c[idx - N5] = 0.f;
    }
}

// ---------------- prep: z2 for all t ----------------
__global__ __launch_bounds__(256) void prep_z2(
    const float* __restrict__ sv, const float* __restrict__ W2, const float* __restrict__ b2)
{
    __shared__ float W2s[10 * 512];
    __shared__ float svs[32 * 10];
    int tid = threadIdx.x;
    for (int idx = tid; idx < 5120; idx += 256)
        W2s[(idx % 10) * 512 + idx / 10] = W2[idx];
    int u0 = blockIdx.x * 32;
    for (int idx = tid; idx < 320; idx += 256) svs[idx] = sv[u0 * 10 + idx];
    __syncthreads();
    int f0 = tid * 2;
    float c0 = b2[f0], c1 = b2[f0 + 1];
    for (int p = 0; p < 32; ++p) {
        int u = u0 + p, bb = u >> 7, tt = u & 127;
        float a0 = c0, a1 = c1;
#pragma unroll
        for (int j = 0; j < 10; ++j) {
            float s = svs[p * 10 + j];
            a0 += s * W2s[j * 512 + f0];
            a1 += s * W2s[j * 512 + f0 + 1];
        }
        u32 hi, lo; split2(fmaxf(a0, 0.f), fmaxf(a1, 0.f), hi, lo);
        size_t off = (size_t)tt * 524288 + (size_t)bb * 512 + f0;
        *(u32*)&Z2hi[off] = hi;
        *(u32*)&Z2lo[off] = lo;
    }
}

// ---------------- fused bf16-split HMMA GEMM ----------------
// MODE 0: z1 = relu([h|c] @ W1^T + b1)      tile 32x64,   128thr, 4-stage, grid (32,8)
// MODE 1: x  = relu([z1|z2_t] @ W3^T + b3)  tile 32x64,   128thr, 4-stage, grid (32,8)
// MODE 2: gates(interleaved) + LSTM cell    tile 128x128, 512thr, 2-stage, grid (8,16)
template <int MODE>
__global__ __launch_bounds__((MODE == 2) ? 512 : 128, 1) void gemm_mma(
    int ping, int t, const float* __restrict__ bias, float* __restrict__ out)
{
    constexpr int MT  = (MODE == 2) ? 128 : 32;
    constexpr int NT  = (MODE == 2) ? 128 : 64;
    constexpr int TH  = (MODE == 2) ? 512 : 128;
    constexpr int NWARP = TH / 32;
    constexpr int WMW = (MODE == 2) ? 4 : 1;
    constexpr int WNW = NWARP / WMW;                 // 4
    constexpr int NFR = (NT / 8) / WNW;              // mode2: 4, else 2
    constexpr int NSTAGE = (MODE == 2) ? 2 : 4;
    constexpr int AH = 0, AL = MT * 128, BH = 2 * MT * 128, BL = 2 * MT * 128 + NT * 128;
    constexpr int STAGE = 2 * MT * 128 + 2 * NT * 128;

    extern __shared__ __align__(16) unsigned char smem[];
    const u32 sb = s2u(smem);
    const int tid = threadIdx.x, lane = tid & 31, wid = tid >> 5;
    const int m0 = blockIdx.x * MT, n0 = blockIdx.y * NT;
    const int wm = wid % WMW, wn = wid / WMW;

    const u16 *A1h, *A1l, *A2h, *A2l, *Wh, *Wl;
    if (MODE == 0) { A1h = Hhi[ping]; A1l = Hlo[ping]; A2h = Chi; A2l = Clo; Wh = W1hi; Wl = W1lo; }
    else if (MODE == 1) {
        size_t zo = (size_t)t * 524288;
        A1h = Z1hi; A1l = Z1lo; A2h = Z2hi + zo; A2l = Z2lo + zo; Wh = W3hi; Wl = W3lo;
    } else { A1h = Xhi; A1l = Xlo; A2h = Hhi[ping]; A2l = Hlo[ping]; Wh = Wghi; Wl = Wglo; }

    float acc[2][NFR][4];
#pragma unroll
    for (int a = 0; a < 2; ++a)
#pragma unroll
        for (int b = 0; b < NFR; ++b)
#pragma unroll
            for (int q = 0; q < 4; ++q) acc[a][b][q] = 0.f;

    auto load_stage = [&](int s) {
        int buf = s % NSTAGE, ks = s * 64, kc = ks & 511;
        const u16* sh = (ks < 512) ? A1h : A2h;
        const u16* sl = (ks < 512) ? A1l : A2l;
        u32 base = sb + (u32)buf * STAGE;
#pragma unroll
        for (int i = tid; i < MT * 8; i += TH) {
            int row = i >> 3, c16 = i & 7;
            size_t g = (size_t)(m0 + row) * 512 + kc + c16 * 8;
            u32 d = swz((u32)(row * 128 + c16 * 16));
            cp16(base + AH + d, sh + g);
            cp16(base + AL + d, sl + g);
        }
#pragma unroll
        for (int i = tid; i < NT * 8; i += TH) {
            int row = i >> 3, c16 = i & 7;
            size_t g = (size_t)(n0 + row) * 1024 + ks + c16 * 8;
            u32 d = swz((u32)(row * 128 + c16 * 16));
            cp16(base + BH + d, Wh + g);
            cp16(base + BL + d, Wl + g);
        }
    };

#pragma unroll
    for (int s = 0; s < NSTAGE - 1; ++s) { load_stage(s); cp_commit(); }

    const int arow = wm * 32 + (lane & 15);
    const int brow = wn * (NFR * 8) + (lane & 15);
    const u32 hi16 = (u32)((lane >> 4) * 16);

    for (int s = 0; s < 16; ++s) {
        if (MODE == 2) {
            // 2-stage: issue next-stage load BEFORE waiting (R5-style overlap, 2 syncs)
            if (s + 1 < 16) { load_stage(s + 1); cp_commit(); cp_wait<1>(); }
            else cp_wait<0>();
            __syncthreads();
        } else {
            // 4-stage: wait for stage s, sync, then refill freed buffer
            cp_wait<NSTAGE - 2>();
            __syncthreads();
            if (s + NSTAGE - 1 < 16) { load_stage(s + NSTAGE - 1); cp_commit(); }
        }
        u32 base = sb + (u32)(s % NSTAGE) * STAGE;

        if (MODE == 2) {
#pragma unroll
            for (int kk = 0; kk < 4; ++kk) {
                u32 kb = (u32)(kk * 32) + hi16;
                u32 Ahr[2][4], Alr[2][4], Bhr[2][4], Blr[2][4];
#pragma unroll
                for (int fm = 0; fm < 2; ++fm) {
                    u32 off = swz((u32)((arow + fm * 16) * 128) + kb);
                    ldsm4(Ahr[fm], base + AH + off);
                    ldsm4(Alr[fm], base + AL + off);
                }
#pragma unroll
                for (int nf = 0; nf < 2; ++nf) {
                    u32 off = swz((u32)((brow + nf * 16) * 128) + kb);
                    ldsm4(Bhr[nf], base + BH + off);
                    ldsm4(Blr[nf], base + BL + off);
                }
#pragma unroll
                for (int fm = 0; fm < 2; ++fm)
#pragma unroll
                    for (int fn = 0; fn < 4; ++fn) {
                        u32 b0 = Bhr[fn >> 1][fn & 1], b1 = Bhr[fn >> 1][(fn & 1) + 2];
                        u32 l0 = Blr[fn >> 1][fn & 1], l1 = Blr[fn >> 1][(fn & 1) + 2];
                        hmma(acc[fm][fn], Ahr[fm], b0, b1);
                        hmma(acc[fm][fn], Ahr[fm], l0, l1);
                        hmma(acc[fm][fn], Alr[fm], b0, b1);
                    }
            }
            __syncthreads();
        } else {
            u32 Ahf[2][2][4], Alf[2][2][4], Bhf[2][4], Blf[2][4];
#define LDFRAG(bf, kk) do { \
            u32 kb = (u32)((kk) * 32) + hi16; \
            ldsm4(Ahf[bf][0], base + AH + swz((u32)(arow * 128) + kb)); \
            ldsm4(Ahf[bf][1], base + AH + swz((u32)((arow + 16) * 128) + kb)); \
            ldsm4(Alf[bf][0], base + AL + swz((u32)(arow * 128) + kb)); \
            ldsm4(Alf[bf][1], base + AL + swz((u32)((arow + 16) * 128) + kb)); \
            ldsm4(Bhf[bf], base + BH + swz((u32)(brow * 128) + kb)); \
            ldsm4(Blf[bf], base + BL + swz((u32)(brow * 128) + kb)); \
        } while (0)
            LDFRAG(0, 0);
#pragma unroll
            for (int kk = 0; kk < 4; ++kk) {
                const int cur = kk & 1;
                if (kk < 3) LDFRAG(cur ^ 1, kk + 1);
#pragma unroll
                for (int fm = 0; fm < 2; ++fm)
#pragma unroll
                    for (int fn = 0; fn < 2; ++fn) {
                        u32 b0 = Bhf[cur][fn], b1 = Bhf[cur][fn + 2];
                        u32 l0 = Blf[cur][fn], l1 = Blf[cur][fn + 2];
                        hmma(acc[fm][fn], Ahf[cur][fm], b0, b1);
                        hmma(acc[fm][fn], Ahf[cur][fm], l0, l1);
                        hmma(acc[fm][fn], Alf[cur][fm], b0, b1);
                    }
            }
#undef LDFRAG
            __syncthreads();
        }
    }

    // ---------------- epilogue ----------------
    if (MODE < 2) {
        u16* Dh = (MODE == 0) ? Z1hi : Xhi;
        u16* Dl = (MODE == 0) ? Z1lo : Xlo;
#pragma unroll
        for (int fm = 0; fm < 2; ++fm)
#pragma unroll
            for (int fn = 0; fn < NFR; ++fn) {
                int c = n0 + wn * (NFR * 8) + fn * 8 + (lane & 3) * 2;
                int r = m0 + wm * 32 + fm * 16 + (lane >> 2);
                float b0 = bias[c], b1v = bias[c + 1];
                u32 hi, lo;
                split2(fmaxf(acc[fm][fn][0] + b0, 0.f), fmaxf(acc[fm][fn][1] + b1v, 0.f), hi, lo);
                *(u32*)&Dh[(size_t)r * 512 + c] = hi;
                *(u32*)&Dl[(size_t)r * 512 + c] = lo;
                split2(fmaxf(acc[fm][fn][2] + b0, 0.f), fmaxf(acc[fm][fn][3] + b1v, 0.f), hi, lo);
                *(u32*)&Dh[(size_t)(r + 8) * 512 + c] = hi;
                *(u32*)&Dl[(size_t)(r + 8) * 512 + c] = lo;
            }
    } else {
        u16* hh = Hhi[ping ^ 1];
        u16* hl = Hlo[ping ^ 1];
        bool odd = lane & 1;
#pragma unroll
        for (int fm = 0; fm < 2; ++fm)
#pragma unroll
            for (int fn = 0; fn < NFR; ++fn) {
                float v0 = acc[fm][fn][0], v1 = acc[fm][fn][1];
                float v2 = acc[fm][fn][2], v3 = acc[fm][fn][3];
                float s0 = __shfl_xor_sync(0xFFFFFFFFu, v0, 1);
                float s1 = __shfl_xor_sync(0xFFFFFFFFu, v1, 1);
                float s2 = __shfl_xor_sync(0xFFFFFFFFu, v2, 1);
                float s3 = __shfl_xor_sync(0xFFFFFFFFu, v3, 1);
                int p = n0 + wn * (NFR * 8) + fn * 8 + (lane & 3) * 2;
                int u = p >> 2;
                int row = m0 + wm * 32 + fm * 16 + (lane >> 2) + (odd ? 8 : 0);
                float gi = odd ? s2 : v0;
                float gf = odd ? s3 : v1;
                float gg = odd ? v2 : s0;
                float go = odd ? v3 : s1;
                int pb = u * 4;
                gi += g_bgp[pb];     gf += g_bgp[pb + 1];
                gg += g_bgp[pb + 2]; go += g_bgp[pb + 3];
                float I = sigf(gi), F = sigf(gf), G = tanhf(gg), O = sigf(go);
                size_t ix = (size_t)row * 512 + u;
                float cn = F * g_c[ix] + I * G;
                float hn = O * tanhf(cn);
                g_c[ix] = cn;
                out[((size_t)row * T_ + t) * 512 + u] = hn;
                u16 hH, hL, cH, cL;
                split1(hn, hH, hL);
                split1(cn, cH, cL);
                hh[ix] = hH; hl[ix] = hL;
                Chi[ix] = cH; Clo[ix] = cL;
            }
    }
}

// ---------------- launch ----------------
extern "C" void kernel_launch(void* const* d_in, const int* in_sizes, int n_in,
                              void* d_out, int out_size)
{
    const float* sv  = (const float*)d_in[0];
    const float* W1  = (const float*)d_in[1];
    const float* b1  = (const float*)d_in[2];
    const float* W2  = (const float*)d_in[3];
    const float* b2  = (const float*)d_in[4];
    const float* W3  = (const float*)d_in[5];
    const float* b3  = (const float*)d_in[6];
    const float* Wih = (const float*)d_in[7];
    const float* Whh = (const float*)d_in[8];
    const float* bih = (const float*)d_in[9];
    const float* bhh = (const float*)d_in[10];
    float* out = (float*)d_out;

    const int SM01 = 4 * (2 * 32 * 128 + 2 * 64 * 128);      // 4 * 24576 = 98304
    const int SM2  = 2 * (2 * 128 * 128 + 2 * 128 * 128);    // 2 * 65536 = 131072
    cudaFuncSetAttribute(gemm_mma<0>, cudaFuncAttributeMaxDynamicSharedMemorySize, SM01);
    cudaFuncSetAttribute(gemm_mma<1>, cudaFuncAttributeMaxDynamicSharedMemorySize, SM01);
    cudaFuncSetAttribute(gemm_mma<2>, cudaFuncAttributeMaxDynamicSharedMemorySize, SM2);

    prep_w<<<2048, 256>>>(W1, W3, Wih, Whh, bih, bhh);
    prep_z2<<<4096, 256>>>(sv, W2, b2);

    dim3 gs(32, 8), gg(8, 16);
    for (int t = 0; t < T_; ++t) {
        int ping = t & 1;
        gemm_mma<0><<<gs, 128, SM01>>>(ping, t, b1, out);
        gemm_mma<1><<<gs, 128, SM01>>>(ping, t, b3, out);
        gemm_mma<2><<<gg, 512, SM2>>>(ping, t, nullptr, out);
    }
}

// round 8
// speedup vs baseline: 1.0628x; 1.0628x over previous
#include <cuda_runtime.h>
#include <cuda_bf16.h>
#include <cstdint>

#define B_ 1024
#define T_ 128

typedef unsigned short u16;
typedef uint32_t u32;

// ---------------- static device buffers (plain row-major, k-contiguous) ----------------
__device__ __align__(16) u16 W1hi[512 * 1024], W1lo[512 * 1024];   // [n][k]
__device__ __align__(16) u16 W3hi[512 * 1024], W3lo[512 * 1024];
__device__ __align__(16) u16 Wghi[2048 * 1024], Wglo[2048 * 1024]; // [p=4i+q][k over x|h]
__device__ __align__(16) u16 Hhi[2][B_ * 512], Hlo[2][B_ * 512];
__device__ __align__(16) u16 Chi[B_ * 512], Clo[B_ * 512];
__device__ __align__(16) u16 Z1hi[B_ * 512], Z1lo[B_ * 512];
__device__ __align__(16) u16 Xhi[B_ * 512],  Xlo[B_ * 512];
__device__ __align__(16) u16 Z2hi[(size_t)T_ * B_ * 512], Z2lo[(size_t)T_ * B_ * 512];
__device__ float g_c[B_ * 512];
__device__ float g_bgp[2048];

// ---------------- helpers ----------------
__device__ __forceinline__ u32 swz(u32 o) { return o ^ ((o >> 3) & 0x70); }
__device__ __forceinline__ u32 s2u(const void* p) {
    u32 a;
    asm("{ .reg .u64 t; cvta.to.shared.u64 t, %1; cvt.u32.u64 %0, t; }" : "=r"(a) : "l"(p));
    return a;
}
__device__ __forceinline__ void cp16(u32 dst, const void* src) {
    asm volatile("cp.async.cg.shared.global [%0], [%1], 16;" :: "r"(dst), "l"(src));
}
__device__ __forceinline__ void cp_commit() { asm volatile("cp.async.commit_group;" ::: "memory"); }
template <int N> __device__ __forceinline__ void cp_wait() {
    asm volatile("cp.async.wait_group %0;" :: "n"(N) : "memory");
}
__device__ __forceinline__ void ldsm4(u32* r, u32 a) {
    asm volatile("ldmatrix.sync.aligned.m8n8.x4.shared.b16 {%0,%1,%2,%3}, [%4];"
                 : "=r"(r[0]), "=r"(r[1]), "=r"(r[2]), "=r"(r[3]) : "r"(a));
}
__device__ __forceinline__ void hmma(float* c, const u32* a, u32 b0, u32 b1) {
    asm volatile("mma.sync.aligned.m16n8k16.row.col.f32.bf16.bf16.f32 "
                 "{%0,%1,%2,%3}, {%4,%5,%6,%7}, {%8,%9}, {%0,%1,%2,%3};"
                 : "+f"(c[0]), "+f"(c[1]), "+f"(c[2]), "+f"(c[3])
                 : "r"(a[0]), "r"(a[1]), "r"(a[2]), "r"(a[3]), "r"(b0), "r"(b1));
}
__device__ __forceinline__ void split1(float v, u16& h, u16& l) {
    __nv_bfloat16 hb = __float2bfloat16(v);
    __nv_bfloat16 lb = __float2bfloat16(v - __bfloat162float(hb));
    h = __bfloat16_as_ushort(hb);
    l = __bfloat16_as_ushort(lb);
}
__device__ __forceinline__ void split2(float a, float b, u32& hi, u32& lo) {
    u16 ah, al, bh, bl;
    split1(a, ah, al); split1(b, bh, bl);
    hi = (u32)ah | ((u32)bh << 16);
    lo = (u32)al | ((u32)bl << 16);
}
__device__ __forceinline__ float sigf(float x) { return 1.f / (1.f + expf(-x)); }

// ---------------- prep: split weights, biases, zero state ----------------
__global__ __launch_bounds__(256) void prep_w(
    const float* __restrict__ W1, const float* __restrict__ W3,
    const float* __restrict__ Wih, const float* __restrict__ Whh,
    const float* __restrict__ bih, const float* __restrict__ bhh)
{
    const int N1 = 524288, N2 = 1048576, N3 = N2 + 2097152;
    const int N4 = N3 + 2048, N5 = N4 + 1048576, N6 = N5 + 524288;
    for (int idx = blockIdx.x * blockDim.x + threadIdx.x; idx < N6;
         idx += gridDim.x * blockDim.x) {
        if (idx < N2) {
            int j = (idx < N1) ? idx : idx - N1;
            float v = (idx < N1) ? W1[j] : W3[j];
            u16 h, l; split1(v, h, l);
            if (idx < N1) { W1hi[j] = h; W1lo[j] = l; }
            else          { W3hi[j] = h; W3lo[j] = l; }
        } else if (idx < N3) {
            int j = idx - N2;
            int p = j >> 10, k = j & 1023;
            int r = (p & 3) * 512 + (p >> 2);
            float v = (k < 512) ? Wih[r * 512 + k] : Whh[r * 512 + (k - 512)];
            u16 h, l; split1(v, h, l);
            Wghi[j] = h; Wglo[j] = l;
        } else if (idx < N4) {
            int p = idx - N3, i = p >> 2, q = p & 3;
            g_bgp[p] = bih[q * 512 + i] + bhh[q * 512 + i];
        } else if (idx < N5) {
            int j = idx - N4;
            int sel = j >> 18, w = j & 262143;
            u16* b = (sel == 0) ? Hhi[0] : (sel == 1) ? Hlo[0] : (sel == 2) ? Chi : Clo;
            *(u32*)&b[w * 2] = 0u;
        } else g_c[idx - N5] = 0.f;
    }
}

// ---------------- prep: z2 for all t ----------------
__global__ __launch_bounds__(256) void prep_z2(
    const float* __restrict__ sv, const float* __restrict__ W2, const float* __restrict__ b2)
{
    __shared__ float W2s[10 * 512];
    __shared__ float svs[32 * 10];
    int tid = threadIdx.x;
    for (int idx = tid; idx < 5120; idx += 256)
        W2s[(idx % 10) * 512 + idx / 10] = W2[idx];
    int u0 = blockIdx.x * 32;
    for (int idx = tid; idx < 320; idx += 256) svs[idx] = sv[u0 * 10 + idx];
    __syncthreads();
    int f0 = tid * 2;
    float c0 = b2[f0], c1 = b2[f0 + 1];
    for (int p = 0; p < 32; ++p) {
        int u = u0 + p, bb = u >> 7, tt = u & 127;
        float a0 = c0, a1 = c1;
#pragma unroll
        for (int j = 0; j < 10; ++j) {
            float s = svs[p * 10 + j];
            a0 += s * W2s[j * 512 + f0];
            a1 += s * W2s[j * 512 + f0 + 1];
        }
        u32 hi, lo; split2(fmaxf(a0, 0.f), fmaxf(a1, 0.f), hi, lo);
        size_t off = (size_t)tt * 524288 + (size_t)bb * 512 + f0;
        *(u32*)&Z2hi[off] = hi;
        *(u32*)&Z2lo[off] = lo;
    }
}

// ---------------- fused bf16-split HMMA GEMM (term-major issue order) ----------------
// MODE 0: z1 = relu([h|c] @ W1^T + b1)      tile 32x64, 128thr, 3-stage, grid (32,8)
// MODE 1: x  = relu([z1|z2_t] @ W3^T + b3)  tile 32x64, 128thr, 3-stage, grid (32,8)
// MODE 2: gates(interleaved) + LSTM cell    tile 128x64, 256thr, 2-stage, grid (8,32)
template <int MODE>
__global__ __launch_bounds__((MODE == 2) ? 256 : 128, 1) void gemm_mma(
    int ping, int t, const float* __restrict__ bias, float* __restrict__ out)
{
    constexpr int MT  = (MODE == 2) ? 128 : 32;
    constexpr int TH  = (MODE == 2) ? 256 : 128;
    constexpr int NWARP = TH / 32;
    constexpr int WMW = (MODE == 2) ? 4 : 1;
    constexpr int WNW = NWARP / WMW;
    constexpr int NFR = 8 / WNW;
    constexpr int NSTAGE = (MODE == 2) ? 2 : 3;
    constexpr int AH = 0, AL = MT * 128, BH = MT * 256, BL = MT * 256 + 8192;
    constexpr int STAGE = MT * 256 + 16384;

    extern __shared__ __align__(16) unsigned char smem[];
    const u32 sb = s2u(smem);
    const int tid = threadIdx.x, lane = tid & 31, wid = tid >> 5;
    const int m0 = blockIdx.x * MT, n0 = blockIdx.y * 64;
    const int wm = wid % WMW, wn = wid / WMW;

    const u16 *A1h, *A1l, *A2h, *A2l, *Wh, *Wl;
    if (MODE == 0) { A1h = Hhi[ping]; A1l = Hlo[ping]; A2h = Chi; A2l = Clo; Wh = W1hi; Wl = W1lo; }
    else if (MODE == 1) {
        size_t zo = (size_t)t * 524288;
        A1h = Z1hi; A1l = Z1lo; A2h = Z2hi + zo; A2l = Z2lo + zo; Wh = W3hi; Wl = W3lo;
    } else { A1h = Xhi; A1l = Xlo; A2h = Hhi[ping]; A2l = Hlo[ping]; Wh = Wghi; Wl = Wglo; }

    float acc[2][NFR][4];
#pragma unroll
    for (int a = 0; a < 2; ++a)
#pragma unroll
        for (int b = 0; b < NFR; ++b)
#pragma unroll
            for (int q = 0; q < 4; ++q) acc[a][b][q] = 0.f;

    auto load_stage = [&](int s) {
        int buf = s % NSTAGE, ks = s * 64, kc = ks & 511;
        const u16* sh = (ks < 512) ? A1h : A2h;
        const u16* sl = (ks < 512) ? A1l : A2l;
        u32 base = sb + (u32)buf * STAGE;
#pragma unroll
        for (int i = tid; i < MT * 8; i += TH) {
            int row = i >> 3, c16 = i & 7;
            size_t g = (size_t)(m0 + row) * 512 + kc + c16 * 8;
            u32 d = swz((u32)(row * 128 + c16 * 16));
            cp16(base + AH + d, sh + g);
            cp16(base + AL + d, sl + g);
        }
#pragma unroll
        for (int i = tid; i < 512; i += TH) {
            int row = i >> 3, c16 = i & 7;
            size_t g = (size_t)(n0 + row) * 1024 + ks + c16 * 8;
            u32 d = swz((u32)(row * 128 + c16 * 16));
            cp16(base + BH + d, Wh + g);
            cp16(base + BL + d, Wl + g);
        }
    };

#pragma unroll
    for (int s = 0; s < NSTAGE - 1; ++s) { load_stage(s); cp_commit(); }

    const int arow = wm * 32 + (lane & 15);
    const int brow = wn * (NFR * 8) + (lane & 15);
    const u32 hi16 = (u32)((lane >> 4) * 16);

    for (int s = 0; s < 16; ++s) {
        cp_wait<NSTAGE - 2>();
        __syncthreads();
        if (s + NSTAGE - 1 < 16) { load_stage(s + NSTAGE - 1); cp_commit(); }
        u32 base = sb + (u32)(s % NSTAGE) * STAGE;

        if (MODE == 2) {
#pragma unroll
            for (int kk = 0; kk < 4; ++kk) {
                u32 kb = (u32)(kk * 32) + hi16;
                u32 Ahr[2][4], Alr[2][4], Bhr[2][4], Blr[2][4];
#pragma unroll
                for (int fm = 0; fm < 2; ++fm) {
                    u32 off = swz((u32)((arow + fm * 16) * 128) + kb);
                    ldsm4(Ahr[fm], base + AH + off);
                    ldsm4(Alr[fm], base + AL + off);
                }
#pragma unroll
                for (int nf = 0; nf < 2; ++nf) {
                    u32 off = swz((u32)((brow + nf * 16) * 128) + kb);
                    ldsm4(Bhr[nf], base + BH + off);
                    ldsm4(Blr[nf], base + BL + off);
                }
                // term-major: all 8 independent accumulators per term (RAW distance 8)
#pragma unroll
                for (int term = 0; term < 3; ++term)
#pragma unroll
                    for (int fm = 0; fm < 2; ++fm)
#pragma unroll
                        for (int fn = 0; fn < 4; ++fn) {
                            const u32* A = (term == 2) ? Alr[fm] : Ahr[fm];
                            u32 b0 = (term == 1) ? Blr[fn >> 1][fn & 1]
                                                 : Bhr[fn >> 1][fn & 1];
                            u32 b1 = (term == 1) ? Blr[fn >> 1][(fn & 1) + 2]
                                                 : Bhr[fn >> 1][(fn & 1) + 2];
                            hmma(acc[fm][fn], A, b0, b1);
                        }
            }
        } else {
            u32 Ahf[2][2][4], Alf[2][2][4], Bhf[2][4], Blf[2][4];
#define LDFRAG(bf, kk) do { \
            u32 kb = (u32)((kk) * 32) + hi16; \
            ldsm4(Ahf[bf][0], base + AH + swz((u32)(arow * 128) + kb)); \
            ldsm4(Ahf[bf][1], base + AH + swz((u32)((arow + 16) * 128) + kb)); \
            ldsm4(Alf[bf][0], base + AL + swz((u32)(arow * 128) + kb)); \
            ldsm4(Alf[bf][1], base + AL + swz((u32)((arow + 16) * 128) + kb)); \
            ldsm4(Bhf[bf], base + BH + swz((u32)(brow * 128) + kb)); \
            ldsm4(Blf[bf], base + BL + swz((u32)(brow * 128) + kb)); \
        } while (0)
            LDFRAG(0, 0);
#pragma unroll
            for (int kk = 0; kk < 4; ++kk) {
                const int cur = kk & 1;
                if (kk < 3) LDFRAG(cur ^ 1, kk + 1);
                // term-major: 4 independent accumulators per term (RAW distance 4)
#pragma unroll
                for (int term = 0; term < 3; ++term)
#pragma unroll
                    for (int fm = 0; fm < 2; ++fm)
#pragma unroll
                        for (int fn = 0; fn < 2; ++fn) {
                            const u32* A = (term == 2) ? Alf[cur][fm] : Ahf[cur][fm];
                            u32 b0 = (term == 1) ? Blf[cur][fn] : Bhf[cur][fn];
                            u32 b1 = (term == 1) ? Blf[cur][fn + 2] : Bhf[cur][fn + 2];
                            hmma(acc[fm][fn], A, b0, b1);
                        }
            }
#undef LDFRAG
        }
        __syncthreads();
    }

    // ---------------- epilogue ----------------
    if (MODE < 2) {
        u16* Dh = (MODE == 0) ? Z1hi : Xhi;
        u16* Dl = (MODE == 0) ? Z1lo : Xlo;
#pragma unroll
        for (int fm = 0; fm < 2; ++fm)
#pragma unroll
            for (int fn = 0; fn < NFR; ++fn) {
                int c = n0 + wn * (NFR * 8) + fn * 8 + (lane & 3) * 2;
                int r = m0 + wm * 32 + fm * 16 + (lane >> 2);
                float b0 = bias[c], b1v = bias[c + 1];
                u32 hi, lo;
                split2(fmaxf(acc[fm][fn][0] + b0, 0.f), fmaxf(acc[fm][fn][1] + b1v, 0.f), hi, lo);
                *(u32*)&Dh[(size_t)r * 512 + c] = hi;
                *(u32*)&Dl[(size_t)r * 512 + c] = lo;
                split2(fmaxf(acc[fm][fn][2] + b0, 0.f), fmaxf(acc[fm][fn][3] + b1v, 0.f), hi, lo);
                *(u32*)&Dh[(size_t)(r + 8) * 512 + c] = hi;
                *(u32*)&Dl[(size_t)(r + 8) * 512 + c] = lo;
            }
    } else {
        u16* hh = Hhi[ping ^ 1];
        u16* hl = Hlo[ping ^ 1];
        bool odd = lane & 1;
#pragma unroll
        for (int fm = 0; fm < 2; ++fm)
#pragma unroll
            for (int fn = 0; fn < NFR; ++fn) {
                float v0 = acc[fm][fn][0], v1 = acc[fm][fn][1];
                float v2 = acc[fm][fn][2], v3 = acc[fm][fn][3];
                float s0 = __shfl_xor_sync(0xFFFFFFFFu, v0, 1);
                float s1 = __shfl_xor_sync(0xFFFFFFFFu, v1, 1);
                float s2 = __shfl_xor_sync(0xFFFFFFFFu, v2, 1);
                float s3 = __shfl_xor_sync(0xFFFFFFFFu, v3, 1);
                int p = n0 + wn * (NFR * 8) + fn * 8 + (lane & 3) * 2;
                int u = p >> 2;
                int row = m0 + wm * 32 + fm * 16 + (lane >> 2) + (odd ? 8 : 0);
                float gi = odd ? s2 : v0;
                float gf = odd ? s3 : v1;
                float gg = odd ? v2 : s0;
                float go = odd ? v3 : s1;
                int pb = u * 4;
                gi += g_bgp[pb];     gf += g_bgp[pb + 1];
                gg += g_bgp[pb + 2]; go += g_bgp[pb + 3];
                float I = sigf(gi), F = sigf(gf), G = tanhf(gg), O = sigf(go);
                size_t ix = (size_t)row * 512 + u;
                float cn = F * g_c[ix] + I * G;
                float hn = O * tanhf(cn);
                g_c[ix] = cn;
                out[((size_t)row * T_ + t) * 512 + u] = hn;
                u16 hH, hL, cH, cL;
                split1(hn, hH, hL);
                split1(cn, cH, cL);
                hh[ix] = hH; hl[ix] = hL;
                Chi[ix] = cH; Clo[ix] = cL;
            }
    }
}

// ---------------- launch ----------------
extern "C" void kernel_launch(void* const* d_in, const int* in_sizes, int n_in,
                              void* d_out, int out_size)
{
    const float* sv  = (const float*)d_in[0];
    const float* W1  = (const float*)d_in[1];
    const float* b1  = (const float*)d_in[2];
    const float* W2  = (const float*)d_in[3];
    const float* b2  = (const float*)d_in[4];
    const float* W3  = (const float*)d_in[5];
    const float* b3  = (const float*)d_in[6];
    const float* Wih = (const float*)d_in[7];
    const float* Whh = (const float*)d_in[8];
    const float* bih = (const float*)d_in[9];
    const float* bhh = (const float*)d_in[10];
    float* out = (float*)d_out;

    const int SM01 = 3 * (32 * 256 + 16384);     // 73728
    const int SM2  = 2 * (128 * 256 + 16384);    // 98304
    cudaFuncSetAttribute(gemm_mma<0>, cudaFuncAttributeMaxDynamicSharedMemorySize, SM01);
    cudaFuncSetAttribute(gemm_mma<1>, cudaFuncAttributeMaxDynamicSharedMemorySize, SM01);
    cudaFuncSetAttribute(gemm_mma<2>, cudaFuncAttributeMaxDynamicSharedMemorySize, SM2);

    prep_w<<<2048, 256>>>(W1, W3, Wih, Whh, bih, bhh);
    prep_z2<<<4096, 256>>>(sv, W2, b2);

    dim3 gs(32, 8), gg(8, 32);
    for (int t = 0; t < T_; ++t) {
        int ping = t & 1;
        gemm_mma<0><<<gs, 128, SM01>>>(ping, t, b1, out);
        gemm_mma<1><<<gs, 128, SM01>>>(ping, t, b3, out);
        gemm_mma<2><<<gg, 256, SM2>>>(ping, t, nullptr, out);
    }
}

// round 10
// speedup vs baseline: 1.0729x; 1.0095x over previous
#include <cuda_runtime.h>
#include <cuda_bf16.h>
#include <cstdint>

#define B_ 1024
#define T_ 128

typedef unsigned short u16;
typedef uint32_t u32;

// ---------------- static device buffers (plain row-major, k-contiguous) ----------------
__device__ __align__(16) u16 W1hi[512 * 1024], W1lo[512 * 1024];   // [n][k]
__device__ __align__(16) u16 W3hi[512 * 1024], W3lo[512 * 1024];
__device__ __align__(16) u16 Wghi[2048 * 1024], Wglo[2048 * 1024]; // [p=4i+q][k over x|h]
__device__ __align__(16) u16 Hhi[2][B_ * 512], Hlo[2][B_ * 512];
__device__ __align__(16) u16 Chi[B_ * 512], Clo[B_ * 512];
__device__ __align__(16) u16 Z1hi[B_ * 512], Z1lo[B_ * 512];
__device__ __align__(16) u16 Xhi[B_ * 512],  Xlo[B_ * 512];
__device__ __align__(16) u16 Z2hi[(size_t)T_ * B_ * 512], Z2lo[(size_t)T_ * B_ * 512];
__device__ float g_c[B_ * 512];
__device__ float g_bgp[2048];

// ---------------- helpers ----------------
__device__ __forceinline__ u32 swz(u32 o) { return o ^ ((o >> 3) & 0x70); }
__device__ __forceinline__ u32 s2u(const void* p) {
    u32 a;
    asm("{ .reg .u64 t; cvta.to.shared.u64 t, %1; cvt.u32.u64 %0, t; }" : "=r"(a) : "l"(p));
    return a;
}
__device__ __forceinline__ void cp16(u32 dst, const void* src) {
    asm volatile("cp.async.cg.shared.global [%0], [%1], 16;" :: "r"(dst), "l"(src));
}
__device__ __forceinline__ void cp_commit() { asm volatile("cp.async.commit_group;" ::: "memory"); }
template <int N> __device__ __forceinline__ void cp_wait() {
    asm volatile("cp.async.wait_group %0;" :: "n"(N) : "memory");
}
__device__ __forceinline__ void ldsm4(u32* r, u32 a) {
    asm volatile("ldmatrix.sync.aligned.m8n8.x4.shared.b16 {%0,%1,%2,%3}, [%4];"
                 : "=r"(r[0]), "=r"(r[1]), "=r"(r[2]), "=r"(r[3]) : "r"(a));
}
__device__ __forceinline__ void hmma(float* c, const u32* a, u32 b0, u32 b1) {
    asm volatile("mma.sync.aligned.m16n8k16.row.col.f32.bf16.bf16.f32 "
                 "{%0,%1,%2,%3}, {%4,%5,%6,%7}, {%8,%9}, {%0,%1,%2,%3};"
                 : "+f"(c[0]), "+f"(c[1]), "+f"(c[2]), "+f"(c[3])
                 : "r"(a[0]), "r"(a[1]), "r"(a[2]), "r"(a[3]), "r"(b0), "r"(b1));
}
__device__ __forceinline__ void split1(float v, u16& h, u16& l) {
    __nv_bfloat16 hb = __float2bfloat16(v);
    __nv_bfloat16 lb = __float2bfloat16(v - __bfloat162float(hb));
    h = __bfloat16_as_ushort(hb);
    l = __bfloat16_as_ushort(lb);
}
__device__ __forceinline__ void split2(float a, float b, u32& hi, u32& lo) {
    u16 ah, al, bh, bl;
    split1(a, ah, al); split1(b, bh, bl);
    hi = (u32)ah | ((u32)bh << 16);
    lo = (u32)al | ((u32)bl << 16);
}
__device__ __forceinline__ float sigf(float x) { return 1.f / (1.f + expf(-x)); }

// ---------------- prep: split weights, biases, zero state ----------------
__global__ __launch_bounds__(256) void prep_w(
    const float* __restrict__ W1, const float* __restrict__ W3,
    const float* __restrict__ Wih, const float* __restrict__ Whh,
    const float* __restrict__ bih, const float* __restrict__ bhh)
{
    const int N1 = 524288, N2 = 1048576, N3 = N2 + 2097152;
    const int N4 = N3 + 2048, N5 = N4 + 1048576, N6 = N5 + 524288;
    for (int idx = blockIdx.x * blockDim.x + threadIdx.x; idx < N6;
         idx += gridDim.x * blockDim.x) {
        if (idx < N2) {
            int j = (idx < N1) ? idx : idx - N1;
            float v = (idx < N1) ? W1[j] : W3[j];
            u16 h, l; split1(v, h, l);
            if (idx < N1) { W1hi[j] = h; W1lo[j] = l; }
            else          { W3hi[j] = h; W3lo[j] = l; }
        } else if (idx < N3) {
            int j = idx - N2;
            int p = j >> 10, k = j & 1023;
            int r = (p & 3) * 512 + (p >> 2);
            float v = (k < 512) ? Wih[r * 512 + k] : Whh[r * 512 + (k - 512)];
            u16 h, l; split1(v, h, l);
            Wghi[j] = h; Wglo[j] = l;
        } else if (idx < N4) {
            int p = idx - N3, i = p >> 2, q = p & 3;
            g_bgp[p] = bih[q * 512 + i] + bhh[q * 512 + i];
        } else if (idx < N5) {
            int j = idx - N4;
            int sel = j >> 18, w = j & 262143;
            u16* b = (sel == 0) ? Hhi[0] : (sel == 1) ? Hlo[0] : (sel == 2) ? Chi : Clo;
            *(u32*)&b[w * 2] = 0u;
        } else g_c[idx - N5] = 0.f;
    }
}

// ---------------- prep: z2 for all t ----------------
__global__ __launch_bounds__(256) void prep_z2(
    const float* __restrict__ sv, const float* __restrict__ W2, const float* __restrict__ b2)
{
    __shared__ float W2s[10 * 512];
    __shared__ float svs[32 * 10];
    int tid = threadIdx.x;
    for (int idx = tid; idx < 5120; idx += 256)
        W2s[(idx % 10) * 512 + idx / 10] = W2[idx];
    int u0 = blockIdx.x * 32;
    for (int idx = tid; idx < 320; idx += 256) svs[idx] = sv[u0 * 10 + idx];
    __syncthreads();
    int f0 = tid * 2;
    float c0 = b2[f0], c1 = b2[f0 + 1];
    for (int p = 0; p < 32; ++p) {
        int u = u0 + p, bb = u >> 7, tt = u & 127;
        float a0 = c0, a1 = c1;
#pragma unroll
        for (int j = 0; j < 10; ++j) {
            float s = svs[p * 10 + j];
            a0 += s * W2s[j * 512 + f0];
            a1 += s * W2s[j * 512 + f0 + 1];
        }
        u32 hi, lo; split2(fmaxf(a0, 0.f), fmaxf(a1, 0.f), hi, lo);
        size_t off = (size_t)tt * 524288 + (size_t)bb * 512 + f0;
        *(u32*)&Z2hi[off] = hi;
        *(u32*)&Z2lo[off] = lo;
    }
}

// ---------------- fused bf16-split HMMA GEMM (TAIL-DRAIN-FIXED pipeline) ----------------
// MODE 0: z1 = relu([h|c] @ W1^T + b1)      tile 32x64, 128thr, 3-stage, grid (16,8)
// MODE 1: x  = relu([z1|z2_t] @ W3^T + b3)  tile 32x64, 128thr, 3-stage, grid (16,8)
// MODE 2: gates(interleaved) + LSTM cell    tile 128x64, 256thr, 2-stage, grid (4,32)
template <int MODE>
__global__ __launch_bounds__((MODE == 2) ? 256 : 128, 1) void gemm_mma(
    int m0g, int ping, int t, const float* __restrict__ bias, float* __restrict__ out)
{
    constexpr int MT  = (MODE == 2) ? 128 : 32;
    constexpr int TH  = (MODE == 2) ? 256 : 128;
    constexpr int NWARP = TH / 32;
    constexpr int WMW = (MODE == 2) ? 4 : 1;
    constexpr int WNW = NWARP / WMW;
    constexpr int NFR = 8 / WNW;
    constexpr int NSTAGE = (MODE == 2) ? 2 : 3;
    constexpr int AH = 0, AL = MT * 128, BH = MT * 256, BL = MT * 256 + 8192;
    constexpr int STAGE = MT * 256 + 16384;

    extern __shared__ __align__(16) unsigned char smem[];
    const u32 sb = s2u(smem);
    const int tid = threadIdx.x, lane = tid & 31, wid = tid >> 5;
    const int m0 = m0g + blockIdx.x * MT, n0 = blockIdx.y * 64;
    const int wm = wid % WMW, wn = wid / WMW;

    const u16 *A1h, *A1l, *A2h, *A2l, *Wh, *Wl;
    if (MODE == 0) { A1h = Hhi[ping]; A1l = Hlo[ping]; A2h = Chi; A2l = Clo; Wh = W1hi; Wl = W1lo; }
    else if (MODE == 1) {
        size_t zo = (size_t)t * 524288;
        A1h = Z1hi; A1l = Z1lo; A2h = Z2hi + zo; A2l = Z2lo + zo; Wh = W3hi; Wl = W3lo;
    } else { A1h = Xhi; A1l = Xlo; A2h = Hhi[ping]; A2l = Hlo[ping]; Wh = Wghi; Wl = Wglo; }

    float acc[2][NFR][4];
#pragma unroll
    for (int a = 0; a < 2; ++a)
#pragma unroll
        for (int b = 0; b < NFR; ++b)
#pragma unroll
            for (int q = 0; q < 4; ++q) acc[a][b][q] = 0.f;

    auto load_stage = [&](int s) {
        int buf = s % NSTAGE, ks = s * 64, kc = ks & 511;
        const u16* sh = (ks < 512) ? A1h : A2h;
        const u16* sl = (ks < 512) ? A1l : A2l;
        u32 base = sb + (u32)buf * STAGE;
#pragma unroll
        for (int i = tid; i < MT * 8; i += TH) {
            int row = i >> 3, c16 = i & 7;
            size_t g = (size_t)(m0 + row) * 512 + kc + c16 * 8;
            u32 d = swz((u32)(row * 128 + c16 * 16));
            cp16(base + AH + d, sh + g);
            cp16(base + AL + d, sl + g);
        }
#pragma unroll
        for (int i = tid; i < 512; i += TH) {
            int row = i >> 3, c16 = i & 7;
            size_t g = (size_t)(n0 + row) * 1024 + ks + c16 * 8;
            u32 d = swz((u32)(row * 128 + c16 * 16));
            cp16(base + BH + d, Wh + g);
            cp16(base + BL + d, Wl + g);
        }
    };

#pragma unroll
    for (int s = 0; s < NSTAGE - 1; ++s) { load_stage(s); cp_commit(); }

    const int arow = wm * 32 + (lane & 15);
    const int brow = wn * (NFR * 8) + (lane & 15);
    const u32 hi16 = (u32)((lane >> 4) * 16);

    for (int s = 0; s < 16; ++s) {
        cp_wait<NSTAGE - 2>();
        __syncthreads();
        if (s + NSTAGE - 1 < 16) load_stage(s + NSTAGE - 1);
        cp_commit();   // UNCONDITIONAL: empty tail groups keep wait<N> aligned (tail-drain fix)
        u32 base = sb + (u32)(s % NSTAGE) * STAGE;

        if (MODE == 2) {
#pragma unroll
            for (int kk = 0; kk < 4; ++kk) {
                u32 kb = (u32)(kk * 32) + hi16;
                u32 Ahr[2][4], Alr[2][4], Bhr[2][4], Blr[2][4];
#pragma unroll
                for (int fm = 0; fm < 2; ++fm) {
                    u32 off = swz((u32)((arow + fm * 16) * 128) + kb);
                    ldsm4(Ahr[fm], base + AH + off);
                    ldsm4(Alr[fm], base + AL + off);
                }
#pragma unroll
                for (int nf = 0; nf < 2; ++nf) {
                    u32 off = swz((u32)((brow + nf * 16) * 128) + kb);
                    ldsm4(Bhr[nf], base + BH + off);
                    ldsm4(Blr[nf], base + BL + off);
                }
#pragma unroll
                for (int term = 0; term < 3; ++term)
#pragma unroll
                    for (int fm = 0; fm < 2; ++fm)
#pragma unroll
                        for (int fn = 0; fn < 4; ++fn) {
                            const u32* A = (term == 2) ? Alr[fm] : Ahr[fm];
                            u32 b0 = (term == 1) ? Blr[fn >> 1][fn & 1]
                                                 : Bhr[fn >> 1][fn & 1];
                            u32 b1 = (term == 1) ? Blr[fn >> 1][(fn & 1) + 2]
                                                 : Bhr[fn >> 1][(fn & 1) + 2];
                            hmma(acc[fm][fn], A, b0, b1);
                        }
            }
        } else {
            u32 Ahf[2][2][4], Alf[2][2][4], Bhf[2][4], Blf[2][4];
#define LDFRAG(bf, kk) do { \
            u32 kb = (u32)((kk) * 32) + hi16; \
            ldsm4(Ahf[bf][0], base + AH + swz((u32)(arow * 128) + kb)); \
            ldsm4(Ahf[bf][1], base + AH + swz((u32)((arow + 16) * 128) + kb)); \
            ldsm4(Alf[bf][0], base + AL + swz((u32)(arow * 128) + kb)); \
            ldsm4(Alf[bf][1], base + AL + swz((u32)((arow + 16) * 128) + kb)); \
            ldsm4(Bhf[bf], base + BH + swz((u32)(brow * 128) + kb)); \
            ldsm4(Blf[bf], base + BL + swz((u32)(brow * 128) + kb)); \
        } while (0)
            LDFRAG(0, 0);
#pragma unroll
            for (int kk = 0; kk < 4; ++kk) {
                const int cur = kk & 1;
                if (kk < 3) LDFRAG(cur ^ 1, kk + 1);
#pragma unroll
                for (int term = 0; term < 3; ++term)
#pragma unroll
                    for (int fm = 0; fm < 2; ++fm)
#pragma unroll
                        for (int fn = 0; fn < 2; ++fn) {
                            const u32* A = (term == 2) ? Alf[cur][fm] : Ahf[cur][fm];
                            u32 b0 = (term == 1) ? Blf[cur][fn] : Bhf[cur][fn];
                            u32 b1 = (term == 1) ? Blf[cur][fn + 2] : Bhf[cur][fn + 2];
                            hmma(acc[fm][fn], A, b0, b1);
                        }
            }
#undef LDFRAG
        }
    }

    // ---------------- epilogue ----------------
    if (MODE < 2) {
        u16* Dh = (MODE == 0) ? Z1hi : Xhi;
        u16* Dl = (MODE == 0) ? Z1lo : Xlo;
#pragma unroll
        for (int fm = 0; fm < 2; ++fm)
#pragma unroll
            for (int fn = 0; fn < NFR; ++fn) {
                int c = n0 + wn * (NFR * 8) + fn * 8 + (lane & 3) * 2;
                int r = m0 + wm * 32 + fm * 16 + (lane >> 2);
                float b0 = bias[c], b1v = bias[c + 1];
                u32 hi, lo;
                split2(fmaxf(acc[fm][fn][0] + b0, 0.f), fmaxf(acc[fm][fn][1] + b1v, 0.f), hi, lo);
                *(u32*)&Dh[(size_t)r * 512 + c] = hi;
                *(u32*)&Dl[(size_t)r * 512 + c] = lo;
                split2(fmaxf(acc[fm][fn][2] + b0, 0.f), fmaxf(acc[fm][fn][3] + b1v, 0.f), hi, lo);
                *(u32*)&Dh[(size_t)(r + 8) * 512 + c] = hi;
                *(u32*)&Dl[(size_t)(r + 8) * 512 + c] = lo;
            }
    } else {
        u16* hh = Hhi[ping ^ 1];
        u16* hl = Hlo[ping ^ 1];
        bool odd = lane & 1;
#pragma unroll
        for (int fm = 0; fm < 2; ++fm)
#pragma unroll
            for (int fn = 0; fn < NFR; ++fn) {
                float v0 = acc[fm][fn][0], v1 = acc[fm][fn][1];
                float v2 = acc[fm][fn][2], v3 = acc[fm][fn][3];
                float s0 = __shfl_xor_sync(0xFFFFFFFFu, v0, 1);
                float s1 = __shfl_xor_sync(0xFFFFFFFFu, v1, 1);
                float s2 = __shfl_xor_sync(0xFFFFFFFFu, v2, 1);
                float s3 = __shfl_xor_sync(0xFFFFFFFFu, v3, 1);
                int p = n0 + wn * (NFR * 8) + fn * 8 + (lane & 3) * 2;
                int u = p >> 2;
                int row = m0 + wm * 32 + fm * 16 + (lane >> 2) + (odd ? 8 : 0);
                float gi = odd ? s2 : v0;
                float gf = odd ? s3 : v1;
                float gg = odd ? v2 : s0;
                float go = odd ? v3 : s1;
                int pb = u * 4;
                gi += g_bgp[pb];     gf += g_bgp[pb + 1];
                gg += g_bgp[pb + 2]; go += g_bgp[pb + 3];
                float I = sigf(gi), F = sigf(gf), G = tanhf(gg), O = sigf(go);
                size_t ix = (size_t)row * 512 + u;
                float cn = F * g_c[ix] + I * G;
                float hn = O * tanhf(cn);
                g_c[ix] = cn;
                out[((size_t)row * T_ + t) * 512 + u] = hn;
                u16 hH, hL, cH, cL;
                split1(hn, hH, hL);
                split1(cn, cH, cL);
                hh[ix] = hH; hl[ix] = hL;
                Chi[ix] = cH; Clo[ix] = cL;
            }
    }
}

// ---------------- launch: 2 independent batch-half chains on 2 streams ----------------
extern "C" void kernel_launch(void* const* d_in, const int* in_sizes, int n_in,
                              void* d_out, int out_size)
{
    const float* sv  = (const float*)d_in[0];
    const float* W1  = (const float*)d_in[1];
    const float* b1  = (const float*)d_in[2];
    const float* W2  = (const float*)d_in[3];
    const float* b2  = (const float*)d_in[4];
    const float* W3  = (const float*)d_in[5];
    const float* b3  = (const float*)d_in[6];
    const float* Wih = (const float*)d_in[7];
    const float* Whh = (const float*)d_in[8];
    const float* bih = (const float*)d_in[9];
    const float* bhh = (const float*)d_in[10];
    float* out = (float*)d_out;

    const int SM01 = 3 * (32 * 256 + 16384);     // 73728
    const int SM2  = 2 * (128 * 256 + 16384);    // 98304

    static cudaStream_t s1 = nullptr;
    static cudaEvent_t ef = nullptr, ej = nullptr;
    if (s1 == nullptr) {
        cudaStreamCreateWithFlags(&s1, cudaStreamNonBlocking);
        cudaEventCreateWithFlags(&ef, cudaEventDisableTiming);
        cudaEventCreateWithFlags(&ej, cudaEventDisableTiming);
        cudaFuncSetAttribute(gemm_mma<0>, cudaFuncAttributeMaxDynamicSharedMemorySize, SM01);
        cudaFuncSetAttribute(gemm_mma<1>, cudaFuncAttributeMaxDynamicSharedMemorySize, SM01);
        cudaFuncSetAttribute(gemm_mma<2>, cudaFuncAttributeMaxDynamicSharedMemorySize, SM2);
    }

    prep_w<<<2048, 256>>>(W1, W3, Wih, Whh, bih, bhh);
    prep_z2<<<4096, 256>>>(sv, W2, b2);

    // fork: stream s1 joins the captured graph after prep
    cudaEventRecord(ef, 0);
    cudaStreamWaitEvent(s1, ef, 0);

    dim3 gs(16, 8), gg(4, 32);
    for (int t = 0; t < T_; ++t) {
        int ping = t & 1;
        // chain 0: rows 0..511 on default stream
        gemm_mma<0><<<gs, 128, SM01, 0>>>(0, ping, t, b1, out);
        gemm_mma<1><<<gs, 128, SM01, 0>>>(0, ping, t, b3, out);
        gemm_mma<2><<<gg, 256, SM2, 0>>>(0, ping, t, nullptr, out);
        // chain 1: rows 512..1023 on s1 (fully independent recurrence)
        gemm_mma<0><<<gs, 128, SM01, s1>>>(512, ping, t, b1, out);
        gemm_mma<1><<<gs, 128, SM01, s1>>>(512, ping, t, b3, out);
        gemm_mma<2><<<gg, 256, SM2, s1>>>(512, ping, t, nullptr, out);
    }

    // join
    cudaEventRecord(ej, s1);
    cudaStreamWaitEvent(0, ej, 0);
}

// round 11
// speedup vs baseline: 1.4197x; 1.3232x over previous
#include <cuda_runtime.h>
#include <cuda_fp16.h>
#include <cstdint>

#define B_ 1024
#define T_ 128

typedef unsigned short u16;
typedef uint32_t u32;

// ---------------- static device buffers ----------------
// weights: fp16 hi+lo pairs ([n][k]); activations: plain fp16 ([m][k])
__device__ __align__(16) u16 W1h[512 * 1024], W1l[512 * 1024];
__device__ __align__(16) u16 W3h[512 * 1024], W3l[512 * 1024];
__device__ __align__(16) u16 Wgh[2048 * 1024], Wgl[2048 * 1024]; // [p=4i+q][k over x|h]
__device__ __align__(16) u16 Hh[2][B_ * 512];
__device__ __align__(16) u16 Ch[B_ * 512];
__device__ __align__(16) u16 Z1h[B_ * 512];
__device__ __align__(16) u16 Xh[B_ * 512];
__device__ __align__(16) u16 Z2h[(size_t)T_ * B_ * 512];
__device__ float g_c[B_ * 512];     // fp32 master cell state
__device__ float g_bgp[2048];

// ---------------- helpers ----------------
__device__ __forceinline__ u32 swz(u32 o) { return o ^ ((o >> 3) & 0x70); }
__device__ __forceinline__ u32 s2u(const void* p) {
    u32 a;
    asm("{ .reg .u64 t; cvta.to.shared.u64 t, %1; cvt.u32.u64 %0, t; }" : "=r"(a) : "l"(p));
    return a;
}
__device__ __forceinline__ void cp16(u32 dst, const void* src) {
    asm volatile("cp.async.cg.shared.global [%0], [%1], 16;" :: "r"(dst), "l"(src));
}
__device__ __forceinline__ void cp_commit() { asm volatile("cp.async.commit_group;" ::: "memory"); }
template <int N> __device__ __forceinline__ void cp_wait() {
    asm volatile("cp.async.wait_group %0;" :: "n"(N) : "memory");
}
__device__ __forceinline__ void ldsm4(u32* r, u32 a) {
    asm volatile("ldmatrix.sync.aligned.m8n8.x4.shared.b16 {%0,%1,%2,%3}, [%4];"
                 : "=r"(r[0]), "=r"(r[1]), "=r"(r[2]), "=r"(r[3]) : "r"(a));
}
__device__ __forceinline__ void hmma(float* c, const u32* a, u32 b0, u32 b1) {
    asm volatile("mma.sync.aligned.m16n8k16.row.col.f32.f16.f16.f32 "
                 "{%0,%1,%2,%3}, {%4,%5,%6,%7}, {%8,%9}, {%0,%1,%2,%3};"
                 : "+f"(c[0]), "+f"(c[1]), "+f"(c[2]), "+f"(c[3])
                 : "r"(a[0]), "r"(a[1]), "r"(a[2]), "r"(a[3]), "r"(b0), "r"(b1));
}
__device__ __forceinline__ void splitw(float v, u16& h, u16& l) {
    __half hh = __float2half_rn(v);
    __half ll = __float2half_rn(v - __half2float(hh));
    h = *(u16*)&hh; l = *(u16*)&ll;
}
__device__ __forceinline__ u16 h1(float v) {
    __half x = __float2half_rn(v);
    return *(u16*)&x;
}
__device__ __forceinline__ u32 pack2h(float a, float b) {
    __half2 p = __floats2half2_rn(a, b);
    return *(u32*)&p;
}
__device__ __forceinline__ float sigf(float x) { return 1.f / (1.f + expf(-x)); }

// ---------------- prep: split weights, biases, zero state ----------------
__global__ __launch_bounds__(256) void prep_w(
    const float* __restrict__ W1, const float* __restrict__ W3,
    const float* __restrict__ Wih, const float* __restrict__ Whh,
    const float* __restrict__ bih, const float* __restrict__ bhh)
{
    const int N1 = 524288, N2 = 1048576, N3 = N2 + 2097152;
    const int N4 = N3 + 2048, N5 = N4 + 524288, N6 = N5 + 524288;
    for (int idx = blockIdx.x * blockDim.x + threadIdx.x; idx < N6;
         idx += gridDim.x * blockDim.x) {
        if (idx < N2) {
            int j = (idx < N1) ? idx : idx - N1;
            float v = (idx < N1) ? W1[j] : W3[j];
            u16 h, l; splitw(v, h, l);
            if (idx < N1) { W1h[j] = h; W1l[j] = l; }
            else          { W3h[j] = h; W3l[j] = l; }
        } else if (idx < N3) {
            int j = idx - N2;
            int p = j >> 10, k = j & 1023;
            int r = (p & 3) * 512 + (p >> 2);
            float v = (k < 512) ? Wih[r * 512 + k] : Whh[r * 512 + (k - 512)];
            u16 h, l; splitw(v, h, l);
            Wgh[j] = h; Wgl[j] = l;
        } else if (idx < N4) {
            int p = idx - N3, i = p >> 2, q = p & 3;
            g_bgp[p] = bih[q * 512 + i] + bhh[q * 512 + i];
        } else if (idx < N5) {
            int j = idx - N4;                 // 524288 words: zero Hh[0] + Ch (u32 words)
            int sel = j >> 18, w = j & 262143;
            u16* b = (sel == 0) ? Hh[0] : Ch;
            *(u32*)&b[w * 2] = 0u;
        } else g_c[idx - N5] = 0.f;
    }
}

// ---------------- prep: z2 for all t (fp16) ----------------
__global__ __launch_bounds__(256) void prep_z2(
    const float* __restrict__ sv, const float* __restrict__ W2, const float* __restrict__ b2)
{
    __shared__ float W2s[10 * 512];
    __shared__ float svs[32 * 10];
    int tid = threadIdx.x;
    for (int idx = tid; idx < 5120; idx += 256)
        W2s[(idx % 10) * 512 + idx / 10] = W2[idx];
    int u0 = blockIdx.x * 32;
    for (int idx = tid; idx < 320; idx += 256) svs[idx] = sv[u0 * 10 + idx];
    __syncthreads();
    int f0 = tid * 2;
    float c0 = b2[f0], c1 = b2[f0 + 1];
    for (int p = 0; p < 32; ++p) {
        int u = u0 + p, bb = u >> 7, tt = u & 127;
        float a0 = c0, a1 = c1;
#pragma unroll
        for (int j = 0; j < 10; ++j) {
            float s = svs[p * 10 + j];
            a0 += s * W2s[j * 512 + f0];
            a1 += s * W2s[j * 512 + f0 + 1];
        }
        size_t off = (size_t)tt * 524288 + (size_t)bb * 512 + f0;
        *(u32*)&Z2h[off] = pack2h(fmaxf(a0, 0.f), fmaxf(a1, 0.f));
    }
}

// ---------------- fused fp16 2-term HMMA GEMM ----------------
// MODE 0: z1 = relu([h|c] @ W1^T + b1)      tile 32x64, 128thr, 3-stage, grid (16,8)
// MODE 1: x  = relu([z1|z2_t] @ W3^T + b3)  tile 32x64, 128thr, 3-stage, grid (16,8)
// MODE 2: gates(interleaved) + LSTM cell    tile 128x64, 256thr, 2-stage, grid (4,32)
template <int MODE>
__global__ __launch_bounds__((MODE == 2) ? 256 : 128, 1) void gemm_mma(
    int m0g, int ping, int t, const float* __restrict__ bias, float* __restrict__ out)
{
    constexpr int MT  = (MODE == 2) ? 128 : 32;
    constexpr int TH  = (MODE == 2) ? 256 : 128;
    constexpr int NWARP = TH / 32;
    constexpr int WMW = (MODE == 2) ? 4 : 1;
    constexpr int WNW = NWARP / WMW;
    constexpr int NFR = 8 / WNW;
    constexpr int NSTAGE = (MODE == 2) ? 2 : 3;
    constexpr int AH = 0, BH = MT * 128, BL = MT * 128 + 8192;
    constexpr int STAGE = MT * 128 + 16384;

    extern __shared__ __align__(16) unsigned char smem[];
    const u32 sb = s2u(smem);
    const int tid = threadIdx.x, lane = tid & 31, wid = tid >> 5;
    const int m0 = m0g + blockIdx.x * MT, n0 = blockIdx.y * 64;
    const int wm = wid % WMW, wn = wid / WMW;

    const u16 *A1, *A2, *Wh, *Wl;
    if (MODE == 0) { A1 = Hh[ping]; A2 = Ch; Wh = W1h; Wl = W1l; }
    else if (MODE == 1) {
        A1 = Z1h; A2 = Z2h + (size_t)t * 524288; Wh = W3h; Wl = W3l;
    } else { A1 = Xh; A2 = Hh[ping]; Wh = Wgh; Wl = Wgl; }

    float acc[2][NFR][4];
#pragma unroll
    for (int a = 0; a < 2; ++a)
#pragma unroll
        for (int b = 0; b < NFR; ++b)
#pragma unroll
            for (int q = 0; q < 4; ++q) acc[a][b][q] = 0.f;

    auto load_stage = [&](int s) {
        int buf = s % NSTAGE, ks = s * 64, kc = ks & 511;
        const u16* sa = (ks < 512) ? A1 : A2;
        u32 base = sb + (u32)buf * STAGE;
#pragma unroll
        for (int i = tid; i < MT * 8; i += TH) {
            int row = i >> 3, c16 = i & 7;
            size_t g = (size_t)(m0 + row) * 512 + kc + c16 * 8;
            u32 d = swz((u32)(row * 128 + c16 * 16));
            cp16(base + AH + d, sa + g);
        }
#pragma unroll
        for (int i = tid; i < 512; i += TH) {
            int row = i >> 3, c16 = i & 7;
            size_t g = (size_t)(n0 + row) * 1024 + ks + c16 * 8;
            u32 d = swz((u32)(row * 128 + c16 * 16));
            cp16(base + BH + d, Wh + g);
            cp16(base + BL + d, Wl + g);
        }
    };

#pragma unroll
    for (int s = 0; s < NSTAGE - 1; ++s) { load_stage(s); cp_commit(); }

    const int arow = wm * 32 + (lane & 15);
    const int brow = wn * (NFR * 8) + (lane & 15);
    const u32 hi16 = (u32)((lane >> 4) * 16);

    for (int s = 0; s < 16; ++s) {
        cp_wait<NSTAGE - 2>();
        __syncthreads();
        if (s + NSTAGE - 1 < 16) load_stage(s + NSTAGE - 1);
        cp_commit();   // unconditional: keeps tail-drain group arithmetic aligned
        u32 base = sb + (u32)(s % NSTAGE) * STAGE;

        if (MODE == 2) {
#pragma unroll
            for (int kk = 0; kk < 4; ++kk) {
                u32 kb = (u32)(kk * 32) + hi16;
                u32 Ar[2][4], Bhr[2][4], Blr[2][4];
#pragma unroll
                for (int fm = 0; fm < 2; ++fm)
                    ldsm4(Ar[fm], base + AH + swz((u32)((arow + fm * 16) * 128) + kb));
#pragma unroll
                for (int nf = 0; nf < 2; ++nf) {
                    u32 off = swz((u32)((brow + nf * 16) * 128) + kb);
                    ldsm4(Bhr[nf], base + BH + off);
                    ldsm4(Blr[nf], base + BL + off);
                }
#pragma unroll
                for (int term = 0; term < 2; ++term)
#pragma unroll
                    for (int fm = 0; fm < 2; ++fm)
#pragma unroll
                        for (int fn = 0; fn < 4; ++fn) {
                            u32 b0 = term ? Blr[fn >> 1][fn & 1] : Bhr[fn >> 1][fn & 1];
                            u32 b1 = term ? Blr[fn >> 1][(fn & 1) + 2] : Bhr[fn >> 1][(fn & 1) + 2];
                            hmma(acc[fm][fn], Ar[fm], b0, b1);
                        }
            }
        } else {
            u32 Af[2][2][4], Bhf[2][4], Blf[2][4];
#define LDFRAG(bf, kk) do { \
            u32 kb = (u32)((kk) * 32) + hi16; \
            ldsm4(Af[bf][0], base + AH + swz((u32)(arow * 128) + kb)); \
            ldsm4(Af[bf][1], base + AH + swz((u32)((arow + 16) * 128) + kb)); \
            ldsm4(Bhf[bf], base + BH + swz((u32)(brow * 128) + kb)); \
            ldsm4(Blf[bf], base + BL + swz((u32)(brow * 128) + kb)); \
        } while (0)
            LDFRAG(0, 0);
#pragma unroll
            for (int kk = 0; kk < 4; ++kk) {
                const int cur = kk & 1;
                if (kk < 3) LDFRAG(cur ^ 1, kk + 1);
#pragma unroll
                for (int term = 0; term < 2; ++term)
#pragma unroll
                    for (int fm = 0; fm < 2; ++fm)
#pragma unroll
                        for (int fn = 0; fn < 2; ++fn) {
                            u32 b0 = term ? Blf[cur][fn] : Bhf[cur][fn];
                            u32 b1 = term ? Blf[cur][fn + 2] : Bhf[cur][fn + 2];
                            hmma(acc[fm][fn], Af[cur][fm], b0, b1);
                        }
            }
#undef LDFRAG
        }
    }

    // ---------------- epilogue ----------------
    if (MODE < 2) {
        u16* Dh = (MODE == 0) ? Z1h : Xh;
#pragma unroll
        for (int fm = 0; fm < 2; ++fm)
#pragma unroll
            for (int fn = 0; fn < NFR; ++fn) {
                int c = n0 + wn * (NFR * 8) + fn * 8 + (lane & 3) * 2;
                int r = m0 + wm * 32 + fm * 16 + (lane >> 2);
                float b0 = bias[c], b1v = bias[c + 1];
                *(u32*)&Dh[(size_t)r * 512 + c] =
                    pack2h(fmaxf(acc[fm][fn][0] + b0, 0.f), fmaxf(acc[fm][fn][1] + b1v, 0.f));
                *(u32*)&Dh[(size_t)(r + 8) * 512 + c] =
                    pack2h(fmaxf(acc[fm][fn][2] + b0, 0.f), fmaxf(acc[fm][fn][3] + b1v, 0.f));
            }
    } else {
        u16* hh = Hh[ping ^ 1];
        bool odd = lane & 1;
#pragma unroll
        for (int fm = 0; fm < 2; ++fm)
#pragma unroll
            for (int fn = 0; fn < NFR; ++fn) {
                float v0 = acc[fm][fn][0], v1 = acc[fm][fn][1];
                float v2 = acc[fm][fn][2], v3 = acc[fm][fn][3];
                float s0 = __shfl_xor_sync(0xFFFFFFFFu, v0, 1);
                float s1 = __shfl_xor_sync(0xFFFFFFFFu, v1, 1);
                float s2 = __shfl_xor_sync(0xFFFFFFFFu, v2, 1);
                float s3 = __shfl_xor_sync(0xFFFFFFFFu, v3, 1);
                int p = n0 + wn * (NFR * 8) + fn * 8 + (lane & 3) * 2;
                int u = p >> 2;
                int row = m0 + wm * 32 + fm * 16 + (lane >> 2) + (odd ? 8 : 0);
                float gi = odd ? s2 : v0;
                float gf = odd ? s3 : v1;
                float gg = odd ? v2 : s0;
                float go = odd ? v3 : s1;
                int pb = u * 4;
                gi += g_bgp[pb];     gf += g_bgp[pb + 1];
                gg += g_bgp[pb + 2]; go += g_bgp[pb + 3];
                float I = sigf(gi), F = sigf(gf), G = tanhf(gg), O = sigf(go);
                size_t ix = (size_t)row * 512 + u;
                float cn = F * g_c[ix] + I * G;
                float hn = O * tanhf(cn);
                g_c[ix] = cn;
                out[((size_t)row * T_ + t) * 512 + u] = hn;
                hh[ix] = h1(hn);
                Ch[ix] = h1(cn);
            }
    }
}

// ---------------- launch: 2 independent batch-half chains on 2 streams ----------------
extern "C" void kernel_launch(void* const* d_in, const int* in_sizes, int n_in,
                              void* d_out, int out_size)
{
    const float* sv  = (const float*)d_in[0];
    const float* W1  = (const float*)d_in[1];
    const float* b1  = (const float*)d_in[2];
    const float* W2  = (const float*)d_in[3];
    const float* b2  = (const float*)d_in[4];
    const float* W3  = (const float*)d_in[5];
    const float* b3  = (const float*)d_in[6];
    const float* Wih = (const float*)d_in[7];
    const float* Whh = (const float*)d_in[8];
    const float* bih = (const float*)d_in[9];
    const float* bhh = (const float*)d_in[10];
    float* out = (float*)d_out;

    const int SM01 = 3 * (32 * 128 + 16384);     // 61440
    const int SM2  = 2 * (128 * 128 + 16384);    // 65536

    static cudaStream_t s1 = nullptr;
    static cudaEvent_t ef = nullptr, ej = nullptr;
    if (s1 == nullptr) {
        cudaStreamCreateWithFlags(&s1, cudaStreamNonBlocking);
        cudaEventCreateWithFlags(&ef, cudaEventDisableTiming);
        cudaEventCreateWithFlags(&ej, cudaEventDisableTiming);
        cudaFuncSetAttribute(gemm_mma<0>, cudaFuncAttributeMaxDynamicSharedMemorySize, SM01);
        cudaFuncSetAttribute(gemm_mma<1>, cudaFuncAttributeMaxDynamicSharedMemorySize, SM01);
        cudaFuncSetAttribute(gemm_mma<2>, cudaFuncAttributeMaxDynamicSharedMemorySize, SM2);
    }

    prep_w<<<2048, 256>>>(W1, W3, Wih, Whh, bih, bhh);
    prep_z2<<<4096, 256>>>(sv, W2, b2);

    cudaEventRecord(ef, 0);
    cudaStreamWaitEvent(s1, ef, 0);

    dim3 gs(16, 8), gg(4, 32);
    for (int t = 0; t < T_; ++t) {
        int ping = t & 1;
        gemm_mma<0><<<gs, 128, SM01, 0>>>(0, ping, t, b1, out);
        gemm_mma<1><<<gs, 128, SM01, 0>>>(0, ping, t, b3, out);
        gemm_mma<2><<<gg, 256, SM2, 0>>>(0, ping, t, nullptr, out);
        gemm_mma<0><<<gs, 128, SM01, s1>>>(512, ping, t, b1, out);
        gemm_mma<1><<<gs, 128, SM01, s1>>>(512, ping, t, b3, out);
        gemm_mma<2><<<gg, 256, SM2, s1>>>(512, ping, t, nullptr, out);
    }

    cudaEventRecord(ej, s1);
    cudaStreamWaitEvent(0, ej, 0);
}